// round 3
// baseline (speedup 1.0000x reference)
#include <cuda_runtime.h>
#include <cstdint>

#define NB   2048
#define CELL 512
#define NK   30
#define LP   1024
#define NV   80
#define N3K  90

// scratch (no device allocation allowed)
__device__ float g_alpha[NB * NK];   // alpha * (L/text_len)
__device__ float g_beta2[NB * NK];   // beta * log2(e)

__device__ __forceinline__ float ex2f(float v) {
    float r;
    asm("ex2.approx.ftz.f32 %0, %1;" : "=f"(r) : "f"(v));
    return r;
}

// ---------------------------------------------------------------------------
// Kernel A: params = exp(x @ W.T + b); split into alpha/beta/kappa.
// grid = NB/8 blocks, 512 threads. Each warp owns output columns j = warp+16m,
// holds W row j in 16 registers, loops over the 8 x-rows cached in shared.
// ---------------------------------------------------------------------------
__global__ void __launch_bounds__(512) kA(
    const float* __restrict__ x, const float* __restrict__ kold,
    const float* __restrict__ tlen, const float* __restrict__ W,
    const float* __restrict__ bias, float* __restrict__ out)
{
    __shared__ __align__(16) float sx[8 * CELL];
    const int warp = threadIdx.x >> 5;
    const int lane = threadIdx.x & 31;
    const int row0 = blockIdx.x * 8;

    for (int i = threadIdx.x; i < 8 * CELL; i += 512)
        sx[i] = x[(size_t)row0 * CELL + i];
    __syncthreads();

    float* okappa = out + (size_t)NB * NV;

    for (int j = warp; j < N3K; j += 16) {
        float wreg[16];
        #pragma unroll
        for (int i = 0; i < 16; i++)
            wreg[i] = W[j * CELL + i * 32 + lane];
        const float bj = bias[j];

        #pragma unroll
        for (int r = 0; r < 8; r++) {
            float acc = 0.f;
            #pragma unroll
            for (int i = 0; i < 16; i++)
                acc = fmaf(wreg[i], sx[r * CELL + i * 32 + lane], acc);
            #pragma unroll
            for (int o = 16; o; o >>= 1)
                acc += __shfl_xor_sync(0xffffffffu, acc, o);
            if (lane == 0) {
                const int row = row0 + r;
                const float p = __expf(acc + bj);
                if (j < NK) {
                    g_alpha[row * NK + j] = p * (1024.0f / tlen[row]);
                } else if (j < 2 * NK) {
                    g_beta2[row * NK + (j - NK)] = p * 1.4426950408889634f;
                } else {
                    const int k = j - 2 * NK;
                    okappa[row * NK + k] = kold[row * NK + k] + p;
                }
            }
        }
    }
}

// ---------------------------------------------------------------------------
// Kernel B: one block per batch row b.
// Phase 1: phi[l] = sum_k alpha'_k * 2^(-beta2_k * (kappa_k - l)^2), l in [0,1024]
// Phase 2: w[v] = sum_{l<1024} phi[l] * onehots[b,l,v]   (671 MB stream, the
//          roofline). float4 coalesced loads, conflict-free private accums.
// ---------------------------------------------------------------------------
#define TB 320   // 20 v-chunks (of float4) x 16 row-groups

__global__ void __launch_bounds__(TB) kB(
    const float* __restrict__ oh, float* __restrict__ out)
{
    __shared__ __align__(16) float sacc[16][NV];     // float4-stored: must be 16B aligned
    __shared__ __align__(16) float sphi[LP + 1];
    __shared__ __align__(16) float sa[NK];
    __shared__ __align__(16) float sb[NK];
    __shared__ __align__(16) float sk[NK];

    const int b = blockIdx.x;
    const int t = threadIdx.x;

    if (t < NK) {
        sa[t] = g_alpha[b * NK + t];
        sb[t] = g_beta2[b * NK + t];
        sk[t] = out[(size_t)NB * NV + (size_t)b * NK + t];  // kappa written by kA
    }
    __syncthreads();

    // --- phi ---
    float* phiout = out + (size_t)NB * NV + (size_t)NB * NK + (size_t)b * (LP + 1);
    for (int l = t; l <= LP; l += TB) {
        const float fl = (float)l;
        float acc = 0.f;
        #pragma unroll
        for (int k = 0; k < NK; k++) {
            const float d = sk[k] - fl;
            const float g = -sb[k] * (d * d);
            acc = fmaf(sa[k], ex2f(g), acc);
        }
        sphi[l] = acc;
        phiout[l] = acc;
    }
    __syncthreads();

    // --- w ---
    // thread t -> fixed v-chunk c = t%20 (4 floats), row group r0 = t/20,
    // rows r0 + 16*j.  Linear float4 index = t + TB*j  (since TB % 20 == 0):
    // fully coalesced, no atomics.
    const int c  = t % 20;
    const int r0 = t / 20;
    const float4* ohb = (const float4*)(oh + (size_t)b * LP * NV);
    float4 a4 = make_float4(0.f, 0.f, 0.f, 0.f);

    #pragma unroll 4
    for (int j = 0; j < 64; j++) {
        const int idx = t + TB * j;
        const float4 v = ohb[idx];
        const float ph = sphi[idx / 20];
        a4.x = fmaf(ph, v.x, a4.x);
        a4.y = fmaf(ph, v.y, a4.y);
        a4.z = fmaf(ph, v.z, a4.z);
        a4.w = fmaf(ph, v.w, a4.w);
    }
    ((float4*)&sacc[r0][0])[c] = a4;
    __syncthreads();

    for (int v = t; v < NV; v += TB) {
        float s = 0.f;
        #pragma unroll
        for (int i = 0; i < 16; i++) s += sacc[i][v];
        out[(size_t)b * NV + v] = s;
    }
}

// ---------------------------------------------------------------------------
extern "C" void kernel_launch(void* const* d_in, const int* in_sizes, int n_in,
                              void* d_out, int out_size)
{
    // positional defaults per metadata order, overridden by unique sizes
    const float* x    = (const float*)d_in[0];
    const float* kold = (n_in > 1) ? (const float*)d_in[1] : nullptr;
    const float* oh   = (n_in > 2) ? (const float*)d_in[2] : nullptr;
    const float* tl   = (n_in > 3) ? (const float*)d_in[3] : nullptr;
    const float* W    = (n_in > 4) ? (const float*)d_in[4] : nullptr;
    const float* bias = (n_in > 5) ? (const float*)d_in[5] : nullptr;

    for (int i = 0; i < n_in; i++) {
        switch (in_sizes[i]) {
            case NB * CELL:            x    = (const float*)d_in[i]; break;  // 1048576
            case NB * NK:              kold = (const float*)d_in[i]; break;  // 61440
            case NB * LP * NV:         oh   = (const float*)d_in[i]; break;  // 167772160
            case NB:                   tl   = (const float*)d_in[i]; break;  // 2048
            case N3K * CELL:           W    = (const float*)d_in[i]; break;  // 46080
            case N3K:                  bias = (const float*)d_in[i]; break;  // 90
            default: break;
        }
    }

    float* out = (float*)d_out;
    kA<<<NB / 8, 512>>>(x, kold, tl, W, bias, out);
    kB<<<NB, TB>>>(oh, out);
}

// round 4
// speedup vs baseline: 1.6198x; 1.6198x over previous
#include <cuda_runtime.h>
#include <cstdint>

#define NB   2048
#define CELL 512
#define NK   30
#define LP   1024
#define NV   80
#define N3K  90

// scratch (no device allocation allowed)
__device__ float g_alpha[NB * NK];   // alpha * (L/text_len)
__device__ float g_beta2[NB * NK];   // beta * log2(e)

__device__ __forceinline__ float ex2f(float v) {
    float r;
    asm("ex2.approx.ftz.f32 %0, %1;" : "=f"(r) : "f"(v));
    return r;
}

// ---------------------------------------------------------------------------
// Kernel A: params = exp(x @ W.T + b); split into alpha/beta/kappa.
// grid = NB/8 blocks, 512 threads. Each warp owns output columns j = warp+16m,
// holds W row j in 16 registers, loops over the 8 x-rows cached in shared.
// ---------------------------------------------------------------------------
__global__ void __launch_bounds__(512) kA(
    const float* __restrict__ x, const float* __restrict__ kold,
    const float* __restrict__ tlen, const float* __restrict__ W,
    const float* __restrict__ bias, float* __restrict__ out)
{
    __shared__ __align__(16) float sx[8 * CELL];
    const int warp = threadIdx.x >> 5;
    const int lane = threadIdx.x & 31;
    const int row0 = blockIdx.x * 8;

    for (int i = threadIdx.x; i < 8 * CELL; i += 512)
        sx[i] = x[(size_t)row0 * CELL + i];
    __syncthreads();

    float* okappa = out + (size_t)NB * NV;

    for (int j = warp; j < N3K; j += 16) {
        float wreg[16];
        #pragma unroll
        for (int i = 0; i < 16; i++)
            wreg[i] = W[j * CELL + i * 32 + lane];
        const float bj = bias[j];

        #pragma unroll
        for (int r = 0; r < 8; r++) {
            float acc = 0.f;
            #pragma unroll
            for (int i = 0; i < 16; i++)
                acc = fmaf(wreg[i], sx[r * CELL + i * 32 + lane], acc);
            #pragma unroll
            for (int o = 16; o; o >>= 1)
                acc += __shfl_xor_sync(0xffffffffu, acc, o);
            if (lane == 0) {
                const int row = row0 + r;
                const float p = __expf(acc + bj);
                if (j < NK) {
                    g_alpha[row * NK + j] = p * (1024.0f / tlen[row]);
                } else if (j < 2 * NK) {
                    g_beta2[row * NK + (j - NK)] = p * 1.4426950408889634f;
                } else {
                    const int k = j - 2 * NK;
                    okappa[row * NK + k] = kold[row * NK + k] + p;
                }
            }
        }
    }
}

// ---------------------------------------------------------------------------
// Kernel B: one block per batch row b.
// Phase 1: phi[l] = sum_k alpha'_k * 2^(-beta2_k * (kappa_k - l)^2)
// Phase 2: w[v] = sum_{l<1024} phi[l] * onehots[b,l,v]  (671 MB stream)
//   thread t -> fixed v-chunk c=t%20 (float4), row r = t/20 + 16*j.
//   Linear float4 index = t + 320*j -> constant-offset coalesced LDG stream.
// ---------------------------------------------------------------------------
#define TB 320   // 20 v-chunks (of float4) x 16 row-groups

__global__ void __launch_bounds__(TB, 2) kB(
    const float* __restrict__ oh, float* __restrict__ out)
{
    __shared__ __align__(16) float sacc[16][NV];
    __shared__ __align__(16) float sphi[LP + 1];
    __shared__ __align__(16) float sa[NK];
    __shared__ __align__(16) float sb[NK];
    __shared__ __align__(16) float sk[NK];

    const int b = blockIdx.x;
    const int t = threadIdx.x;

    if (t < NK) {
        sa[t] = g_alpha[b * NK + t];
        sb[t] = g_beta2[b * NK + t];
        sk[t] = out[(size_t)NB * NV + (size_t)b * NK + t];  // kappa from kA
    }
    __syncthreads();

    // --- phi ---
    float* phiout = out + (size_t)NB * NV + (size_t)NB * NK + (size_t)b * (LP + 1);
    for (int l = t; l <= LP; l += TB) {
        const float fl = (float)l;
        float acc = 0.f;
        #pragma unroll
        for (int k = 0; k < NK; k++) {
            const float d = sk[k] - fl;
            const float g = -sb[k] * (d * d);
            acc = fmaf(sa[k], ex2f(g), acc);
        }
        sphi[l] = acc;
        phiout[l] = acc;
    }
    __syncthreads();

    // --- w streaming ---
    const int c  = t % 20;
    const int r0 = t / 20;
    const float4* ohb = (const float4*)(oh + (size_t)b * LP * NV) + t;

    float4 a0 = make_float4(0.f, 0.f, 0.f, 0.f);
    float4 a1 = make_float4(0.f, 0.f, 0.f, 0.f);

    #pragma unroll
    for (int j = 0; j < 64; j += 8) {
        float4 v[8];
        #pragma unroll
        for (int u = 0; u < 8; u++)
            v[u] = __ldcs(ohb + (size_t)(j + u) * TB);
        float ph[8];
        #pragma unroll
        for (int u = 0; u < 8; u++)
            ph[u] = sphi[r0 + 16 * (j + u)];
        #pragma unroll
        for (int u = 0; u < 8; u++) {
            float4& a = (u & 1) ? a1 : a0;
            a.x = fmaf(ph[u], v[u].x, a.x);
            a.y = fmaf(ph[u], v[u].y, a.y);
            a.z = fmaf(ph[u], v[u].z, a.z);
            a.w = fmaf(ph[u], v[u].w, a.w);
        }
    }
    a0.x += a1.x; a0.y += a1.y; a0.z += a1.z; a0.w += a1.w;
    ((float4*)&sacc[r0][0])[c] = a0;
    __syncthreads();

    for (int v = t; v < NV; v += TB) {
        float s = 0.f;
        #pragma unroll
        for (int i = 0; i < 16; i++) s += sacc[i][v];
        out[(size_t)b * NV + v] = s;
    }
}

// ---------------------------------------------------------------------------
extern "C" void kernel_launch(void* const* d_in, const int* in_sizes, int n_in,
                              void* d_out, int out_size)
{
    const float* x    = (const float*)d_in[0];
    const float* kold = (n_in > 1) ? (const float*)d_in[1] : nullptr;
    const float* oh   = (n_in > 2) ? (const float*)d_in[2] : nullptr;
    const float* tl   = (n_in > 3) ? (const float*)d_in[3] : nullptr;
    const float* W    = (n_in > 4) ? (const float*)d_in[4] : nullptr;
    const float* bias = (n_in > 5) ? (const float*)d_in[5] : nullptr;

    for (int i = 0; i < n_in; i++) {
        switch (in_sizes[i]) {
            case NB * CELL:            x    = (const float*)d_in[i]; break;
            case NB * NK:              kold = (const float*)d_in[i]; break;
            case NB * LP * NV:         oh   = (const float*)d_in[i]; break;
            case NB:                   tl   = (const float*)d_in[i]; break;
            case N3K * CELL:           W    = (const float*)d_in[i]; break;
            case N3K:                  bias = (const float*)d_in[i]; break;
            default: break;
        }
    }

    float* out = (float*)d_out;
    kA<<<NB / 8, 512>>>(x, kold, tl, W, bias, out);
    kB<<<NB, TB>>>(oh, out);
}

// round 5
// speedup vs baseline: 1.6986x; 1.0486x over previous
#include <cuda_runtime.h>
#include <cstdint>

#define NB   2048
#define CELL 512
#define NK   30
#define LP   1024
#define NV   80
#define N3K  90

// scratch (no device allocation allowed)
__device__ float g_alpha[NB * NK];   // alpha * (L/text_len)
__device__ float g_beta2[NB * NK];   // beta * log2(e)

__device__ __forceinline__ float ex2f(float v) {
    float r;
    asm("ex2.approx.ftz.f32 %0, %1;" : "=f"(r) : "f"(v));
    return r;
}

// ---------------------------------------------------------------------------
// Kernel A: params = exp(x @ W.T + b) -> alpha/beta/kappa.
// grid = NB/8, 512 threads. Warp w owns j = w + 16m (6 iters, j<90 guarded).
// float4 loads for W and x; butterfly reduce leaves sum in all lanes; the 8
// row sums are spread across lanes 0-7 so ONE expf (8 active lanes) replaces
// 8 warp-serial ones.
// ---------------------------------------------------------------------------
__global__ void __launch_bounds__(512) kA(
    const float* __restrict__ x, const float* __restrict__ kold,
    const float* __restrict__ tlen, const float* __restrict__ W,
    const float* __restrict__ bias, float* __restrict__ out)
{
    __shared__ __align__(16) float sx[8 * CELL];
    const int warp = threadIdx.x >> 5;
    const int lane = threadIdx.x & 31;
    const int row0 = blockIdx.x * 8;

    // coalesced float4 fill of 8 x-rows
    {
        const float4* xs = (const float4*)(x + (size_t)row0 * CELL);
        float4* sx4 = (float4*)sx;
        for (int i = threadIdx.x; i < 8 * (CELL / 4); i += 512)
            sx4[i] = xs[i];
    }
    __syncthreads();

    float* okappa = out + (size_t)NB * NV;

    #pragma unroll
    for (int jj = 0; jj < 6; jj++) {
        const int j = warp + 16 * jj;
        if (j >= N3K) continue;

        // W row j: 4 float4 per lane at positions k*128 + lane*4
        const float4* wp = (const float4*)(W + (size_t)j * CELL) + lane;
        float4 w0 = wp[0], w1 = wp[32], w2 = wp[64], w3 = wp[96];
        const float bj = bias[j];

        float accs[8];
        #pragma unroll
        for (int r = 0; r < 8; r++) {
            const float4* sp = (const float4*)sx + r * (CELL / 4) + lane;
            float4 x0 = sp[0], x1 = sp[32], x2 = sp[64], x3 = sp[96];
            float a = w0.x * x0.x;
            a = fmaf(w0.y, x0.y, a); a = fmaf(w0.z, x0.z, a); a = fmaf(w0.w, x0.w, a);
            a = fmaf(w1.x, x1.x, a); a = fmaf(w1.y, x1.y, a);
            a = fmaf(w1.z, x1.z, a); a = fmaf(w1.w, x1.w, a);
            a = fmaf(w2.x, x2.x, a); a = fmaf(w2.y, x2.y, a);
            a = fmaf(w2.z, x2.z, a); a = fmaf(w2.w, x2.w, a);
            a = fmaf(w3.x, x3.x, a); a = fmaf(w3.y, x3.y, a);
            a = fmaf(w3.z, x3.z, a); a = fmaf(w3.w, x3.w, a);
            #pragma unroll
            for (int o = 16; o; o >>= 1)
                a += __shfl_xor_sync(0xffffffffu, a, o);
            accs[r] = a;   // all lanes hold row r's full sum
        }

        // spread rows across lanes 0-7, single expf
        float v = accs[0];
        #pragma unroll
        for (int r = 1; r < 8; r++)
            if (lane == r) v = accs[r];

        if (lane < 8) {
            const int row = row0 + lane;
            const float p = __expf(v + bj);
            if (j < NK) {
                g_alpha[row * NK + j] = p * (1024.0f / tlen[row]);
            } else if (j < 2 * NK) {
                g_beta2[row * NK + (j - NK)] = p * 1.4426950408889634f;
            } else {
                const int k = j - 2 * NK;
                okappa[row * NK + k] = kold[row * NK + k] + p;
            }
        }
    }
}

// ---------------------------------------------------------------------------
// Kernel B: one block per batch row b. (unchanged — ~92% of LTS ceiling)
// ---------------------------------------------------------------------------
#define TB 320   // 20 v-chunks (of float4) x 16 row-groups

__global__ void __launch_bounds__(TB, 2) kB(
    const float* __restrict__ oh, float* __restrict__ out)
{
    __shared__ __align__(16) float sacc[16][NV];
    __shared__ __align__(16) float sphi[LP + 1];
    __shared__ __align__(16) float sa[NK];
    __shared__ __align__(16) float sb[NK];
    __shared__ __align__(16) float sk[NK];

    const int b = blockIdx.x;
    const int t = threadIdx.x;

    if (t < NK) {
        sa[t] = g_alpha[b * NK + t];
        sb[t] = g_beta2[b * NK + t];
        sk[t] = out[(size_t)NB * NV + (size_t)b * NK + t];  // kappa from kA
    }
    __syncthreads();

    // --- phi ---
    float* phiout = out + (size_t)NB * NV + (size_t)NB * NK + (size_t)b * (LP + 1);
    for (int l = t; l <= LP; l += TB) {
        const float fl = (float)l;
        float acc = 0.f;
        #pragma unroll
        for (int k = 0; k < NK; k++) {
            const float d = sk[k] - fl;
            const float g = -sb[k] * (d * d);
            acc = fmaf(sa[k], ex2f(g), acc);
        }
        sphi[l] = acc;
        phiout[l] = acc;
    }
    __syncthreads();

    // --- w streaming ---
    const int c  = t % 20;
    const int r0 = t / 20;
    const float4* ohb = (const float4*)(oh + (size_t)b * LP * NV) + t;

    float4 a0 = make_float4(0.f, 0.f, 0.f, 0.f);
    float4 a1 = make_float4(0.f, 0.f, 0.f, 0.f);

    #pragma unroll
    for (int j = 0; j < 64; j += 8) {
        float4 v[8];
        #pragma unroll
        for (int u = 0; u < 8; u++)
            v[u] = __ldcs(ohb + (size_t)(j + u) * TB);
        float ph[8];
        #pragma unroll
        for (int u = 0; u < 8; u++)
            ph[u] = sphi[r0 + 16 * (j + u)];
        #pragma unroll
        for (int u = 0; u < 8; u++) {
            float4& a = (u & 1) ? a1 : a0;
            a.x = fmaf(ph[u], v[u].x, a.x);
            a.y = fmaf(ph[u], v[u].y, a.y);
            a.z = fmaf(ph[u], v[u].z, a.z);
            a.w = fmaf(ph[u], v[u].w, a.w);
        }
    }
    a0.x += a1.x; a0.y += a1.y; a0.z += a1.z; a0.w += a1.w;
    ((float4*)&sacc[r0][0])[c] = a0;
    __syncthreads();

    for (int v = t; v < NV; v += TB) {
        float s = 0.f;
        #pragma unroll
        for (int i = 0; i < 16; i++) s += sacc[i][v];
        out[(size_t)b * NV + v] = s;
    }
}

// ---------------------------------------------------------------------------
extern "C" void kernel_launch(void* const* d_in, const int* in_sizes, int n_in,
                              void* d_out, int out_size)
{
    const float* x    = (const float*)d_in[0];
    const float* kold = (n_in > 1) ? (const float*)d_in[1] : nullptr;
    const float* oh   = (n_in > 2) ? (const float*)d_in[2] : nullptr;
    const float* tl   = (n_in > 3) ? (const float*)d_in[3] : nullptr;
    const float* W    = (n_in > 4) ? (const float*)d_in[4] : nullptr;
    const float* bias = (n_in > 5) ? (const float*)d_in[5] : nullptr;

    for (int i = 0; i < n_in; i++) {
        switch (in_sizes[i]) {
            case NB * CELL:            x    = (const float*)d_in[i]; break;
            case NB * NK:              kold = (const float*)d_in[i]; break;
            case NB * LP * NV:         oh   = (const float*)d_in[i]; break;
            case NB:                   tl   = (const float*)d_in[i]; break;
            case N3K * CELL:           W    = (const float*)d_in[i]; break;
            case N3K:                  bias = (const float*)d_in[i]; break;
            default: break;
        }
    }

    float* out = (float*)d_out;
    kA<<<NB / 8, 512>>>(x, kold, tl, W, bias, out);
    kB<<<NB, TB>>>(oh, out);
}

// round 6
// speedup vs baseline: 1.7553x; 1.0334x over previous
#include <cuda_runtime.h>
#include <cstdint>

#define NB   2048
#define CELL 512
#define NK   30
#define LP   1024
#define NV   80
#define N3K  90

__device__ __forceinline__ float ex2f(float v) {
    float r;
    asm("ex2.approx.ftz.f32 %0, %1;" : "=f"(r) : "f"(v));
    return r;
}

// ---------------------------------------------------------------------------
// Fused kernel: one block per batch row b.
// Phase 0: params = exp(x[b] @ W.T + b) -> alpha'/beta'/kappa (in shared).
//          warp w computes j = 9w .. 9w+8 (10 warps x 9 = 90). Results spread
//          across lanes -> ONE 9-lane expf per warp. W is L2-resident after
//          wave 0 (184 KB).
// Phase 1: phi[l] = sum_k alpha'_k * 2^(-beta'_k (kappa_k - l)^2), l in [0,1024]
// Phase 2: w[v] = sum_l phi[l] * onehots[b,l,v]   -- the 671 MB HBM stream.
//          thread t -> v-chunk c=t%20 (float4), rows r0=t/20 + 16j;
//          linear float4 idx = t + 320j (constant-offset coalesced stream).
// ---------------------------------------------------------------------------
#define TB 320   // 20 v-chunks x 16 row-groups

__global__ void __launch_bounds__(TB, 2) kFused(
    const float* __restrict__ x,  const float* __restrict__ kold,
    const float* __restrict__ oh, const float* __restrict__ tlen,
    const float* __restrict__ W,  const float* __restrict__ bias,
    float* __restrict__ out)
{
    __shared__ __align__(16) float sacc[16][NV];
    __shared__ __align__(16) float sphi[LP + 1];
    __shared__ __align__(16) float sx[CELL];
    __shared__ __align__(16) float sraw[N3K + 6];  // exp(x@W.T+b), padded
    __shared__ __align__(16) float sa[NK];
    __shared__ __align__(16) float sb[NK];
    __shared__ __align__(16) float sk[NK];

    const int b    = blockIdx.x;
    const int t    = threadIdx.x;
    const int warp = t >> 5;
    const int lane = t & 31;

    // ---- Phase 0a: stage x row ----
    {
        const float4* xr = (const float4*)(x + (size_t)b * CELL);
        float4* sx4 = (float4*)sx;
        for (int i = t; i < CELL / 4; i += TB) sx4[i] = xr[i];
    }
    __syncthreads();

    // ---- Phase 0b: 90 dot products, 9 per warp ----
    {
        float accs[9];
        #pragma unroll
        for (int i = 0; i < 9; i++) {
            const int j = warp * 9 + i;
            const float4* wp = (const float4*)(W + (size_t)j * CELL) + lane;
            const float4* sp = (const float4*)sx + lane;
            float4 w0 = wp[0], w1 = wp[32], w2 = wp[64], w3 = wp[96];
            float4 x0 = sp[0], x1 = sp[32], x2 = sp[64], x3 = sp[96];
            float a = w0.x * x0.x;
            a = fmaf(w0.y, x0.y, a); a = fmaf(w0.z, x0.z, a); a = fmaf(w0.w, x0.w, a);
            a = fmaf(w1.x, x1.x, a); a = fmaf(w1.y, x1.y, a);
            a = fmaf(w1.z, x1.z, a); a = fmaf(w1.w, x1.w, a);
            a = fmaf(w2.x, x2.x, a); a = fmaf(w2.y, x2.y, a);
            a = fmaf(w2.z, x2.z, a); a = fmaf(w2.w, x2.w, a);
            a = fmaf(w3.x, x3.x, a); a = fmaf(w3.y, x3.y, a);
            a = fmaf(w3.z, x3.z, a); a = fmaf(w3.w, x3.w, a);
            #pragma unroll
            for (int o = 16; o; o >>= 1)
                a += __shfl_xor_sync(0xffffffffu, a, o);
            accs[i] = a;               // all lanes hold sum for j
        }
        // spread 9 results across lanes 0-8, single expf
        float v = accs[0];
        #pragma unroll
        for (int i = 1; i < 9; i++)
            if (lane == i) v = accs[i];
        if (lane < 9) {
            const int j = warp * 9 + lane;
            sraw[j] = __expf(v + bias[j]);
        }
    }
    __syncthreads();

    // ---- Phase 0c: derive alpha'/beta'/kappa; write kappa out ----
    if (t < NK) {
        const float inv = 1024.0f / tlen[b];
        sa[t] = sraw[t] * inv;
        sb[t] = sraw[NK + t] * 1.4426950408889634f;
        const float kap = kold[b * NK + t] + sraw[2 * NK + t];
        sk[t] = kap;
        out[(size_t)NB * NV + (size_t)b * NK + t] = kap;
    }
    __syncthreads();

    // ---- Phase 1: phi ----
    float* phiout = out + (size_t)NB * NV + (size_t)NB * NK + (size_t)b * (LP + 1);
    for (int l = t; l <= LP; l += TB) {
        const float fl = (float)l;
        float acc = 0.f;
        #pragma unroll
        for (int k = 0; k < NK; k++) {
            const float d = sk[k] - fl;
            const float g = -sb[k] * (d * d);
            acc = fmaf(sa[k], ex2f(g), acc);
        }
        sphi[l] = acc;
        phiout[l] = acc;
    }
    __syncthreads();

    // ---- Phase 2: w streaming ----
    const int c  = t % 20;
    const int r0 = t / 20;
    const float4* ohb = (const float4*)(oh + (size_t)b * LP * NV) + t;

    float4 a0 = make_float4(0.f, 0.f, 0.f, 0.f);
    float4 a1 = make_float4(0.f, 0.f, 0.f, 0.f);

    #pragma unroll
    for (int j = 0; j < 64; j += 8) {
        float4 v[8];
        #pragma unroll
        for (int u = 0; u < 8; u++)
            v[u] = __ldcs(ohb + (size_t)(j + u) * TB);
        float ph[8];
        #pragma unroll
        for (int u = 0; u < 8; u++)
            ph[u] = sphi[r0 + 16 * (j + u)];
        #pragma unroll
        for (int u = 0; u < 8; u++) {
            float4& a = (u & 1) ? a1 : a0;
            a.x = fmaf(ph[u], v[u].x, a.x);
            a.y = fmaf(ph[u], v[u].y, a.y);
            a.z = fmaf(ph[u], v[u].z, a.z);
            a.w = fmaf(ph[u], v[u].w, a.w);
        }
    }
    a0.x += a1.x; a0.y += a1.y; a0.z += a1.z; a0.w += a1.w;
    ((float4*)&sacc[r0][0])[c] = a0;
    __syncthreads();

    for (int v = t; v < NV; v += TB) {
        float s = 0.f;
        #pragma unroll
        for (int i = 0; i < 16; i++) s += sacc[i][v];
        out[(size_t)b * NV + v] = s;
    }
}

// ---------------------------------------------------------------------------
extern "C" void kernel_launch(void* const* d_in, const int* in_sizes, int n_in,
                              void* d_out, int out_size)
{
    const float* x    = (const float*)d_in[0];
    const float* kold = (n_in > 1) ? (const float*)d_in[1] : nullptr;
    const float* oh   = (n_in > 2) ? (const float*)d_in[2] : nullptr;
    const float* tl   = (n_in > 3) ? (const float*)d_in[3] : nullptr;
    const float* W    = (n_in > 4) ? (const float*)d_in[4] : nullptr;
    const float* bias = (n_in > 5) ? (const float*)d_in[5] : nullptr;

    for (int i = 0; i < n_in; i++) {
        switch (in_sizes[i]) {
            case NB * CELL:            x    = (const float*)d_in[i]; break;
            case NB * NK:              kold = (const float*)d_in[i]; break;
            case NB * LP * NV:         oh   = (const float*)d_in[i]; break;
            case NB:                   tl   = (const float*)d_in[i]; break;
            case N3K * CELL:           W    = (const float*)d_in[i]; break;
            case N3K:                  bias = (const float*)d_in[i]; break;
            default: break;
        }
    }

    float* out = (float*)d_out;
    kFused<<<NB, TB>>>(x, kold, oh, tl, W, bias, out);
}